// round 16
// baseline (speedup 1.0000x reference)
#include <cuda_runtime.h>
#include <cuda_fp16.h>
#include <cstdint>

// GlobalAggregator: B=256, N=256, K=16, DIM=128
// TBN=4 (M=64), cp.async double-buffered, 2 CTAs/SM, 3 syncs/tile.
// RACE-SAFE: next-tile cp.async issued only AFTER sync 1 (the barrier that proves
// all threads finished reading the destination buffer in the previous iteration).
//  - B (w1^T fp16) frags persistent in regs per warp (16-e strip, 32 regs)
//  - epilogue: all 8 warps redundantly reduce+softmax (shfl), output 2 floats/thread

#define DIMX 128
#define KN   16
#define TBN  4
#define NTHREADS 256
#define ASTRIDE 272          // bytes per A/Bt row (128 fp16 + 8 pad)

#define SM_A     0           // 64 x 272 = 17408 (Bt spans A+RAW0 during init)
#define SM_RAW0  17408       // 64x128 f32 = 32768
#define SM_RAW1  50176       // 32768
#define SM_EX    82944       // 2 bufs x 512 f32 = 4096
#define SM_WT    87040       // 2 bufs x 64 f32 = 512
#define SM_PART  87552       // 8 x 64 f32 = 2048
#define SM_BIAS  89600       // 128 f32
#define SM_W2    90112       // 128 f32
#define SM_TOTAL 90624

static __device__ __forceinline__ uint32_t smem_u32(const void* p) {
    uint32_t a;
    asm("{ .reg .u64 t; cvta.to.shared.u64 t, %1; cvt.u32.u64 %0, t; }" : "=r"(a) : "l"(p));
    return a;
}
static __device__ __forceinline__ void cp16(uint32_t saddr, const void* g) {
    asm volatile("cp.async.cg.shared.global [%0], [%1], 16;" :: "r"(saddr), "l"(g));
}
static __device__ __forceinline__ void cp_commit() {
    asm volatile("cp.async.commit_group;" ::: "memory");
}
static __device__ __forceinline__ void cp_wait_all() {
    asm volatile("cp.async.wait_group 0;" ::: "memory");
}
static __device__ __forceinline__ void ldsm4(uint32_t& r0, uint32_t& r1, uint32_t& r2, uint32_t& r3,
                                             uint32_t addr) {
    asm volatile("ldmatrix.sync.aligned.m8n8.x4.shared.b16 {%0,%1,%2,%3}, [%4];"
                 : "=r"(r0), "=r"(r1), "=r"(r2), "=r"(r3) : "r"(addr));
}
static __device__ __forceinline__ void mma_f16(float& c0, float& c1, float& c2, float& c3,
                                               uint32_t a0, uint32_t a1, uint32_t a2, uint32_t a3,
                                               uint32_t b0, uint32_t b1) {
    asm volatile("mma.sync.aligned.m16n8k16.row.col.f32.f16.f16.f32 "
                 "{%0,%1,%2,%3},{%4,%5,%6,%7},{%8,%9},{%0,%1,%2,%3};"
                 : "+f"(c0), "+f"(c1), "+f"(c2), "+f"(c3)
                 : "r"(a0), "r"(a1), "r"(a2), "r"(a3), "r"(b0), "r"(b1));
}
static __device__ __forceinline__ uint32_t pack_h2(float x, float y) {
    __half2 h(__float2half_rn(x), __float2half_rn(y));
    return *(uint32_t*)&h;
}
__device__ __forceinline__ float leaky02(float v) { return v > 0.0f ? v : 0.2f * v; }

extern "C" __global__ void __launch_bounds__(NTHREADS, 2)
agg_mma_kernel(const float* __restrict__ neighbor,
               const float* __restrict__ nweight,
               const float* __restrict__ extra,
               const float* __restrict__ w1,
               const float* __restrict__ w2,
               float* __restrict__ out,
               int ntiles)
{
    extern __shared__ __align__(16) char smem[];
    const uint32_t sbase = smem_u32(smem);
    const int tid  = threadIdx.x;
    const int warp = tid >> 5;
    const int lane = tid & 31;

    float* part  = (float*)(smem + SM_PART);
    float* biass = (float*)(smem + SM_BIAS);
    float* w2s   = (float*)(smem + SM_W2);

    // ---- phase 0: build Bt (w1^T fp16) across A+RAW0 region (init only) ----
    for (int idx = tid; idx < DIMX * DIMX; idx += NTHREADS) {
        int d = idx >> 7;
        int e = idx & 127;
        *(__half*)(smem + (uint32_t)e * ASTRIDE + (uint32_t)d * 2) = __float2half_rn(w1[idx]);
    }
    if (tid < DIMX) {
        biass[tid] = w1[DIMX * DIMX + tid];
        w2s[tid]   = w2[tid];
    }
    __syncthreads();

    // ---- persistent B frags: warp's 16-e strip, 8 kc chunks (32 regs) ----
    uint32_t bb[8][4];
    {
        const uint32_t bfbase = sbase
            + (uint32_t)(warp * 16 + (lane & 7) + ((lane >> 4) & 1) * 8) * ASTRIDE
            + ((lane >> 3) & 1) * 16;
        #pragma unroll
        for (int kc = 0; kc < 8; ++kc)
            ldsm4(bb[kc][0], bb[kc][1], bb[kc][2], bb[kc][3], bfbase + kc * 32);
    }
    __syncthreads();   // Bt consumed; region becomes A tile + raw buffers

    const int stride = gridDim.x;

    // ---- prologue: stream first tile into buffer 0 ----
    {
        int t0 = blockIdx.x;
        if (t0 < ntiles) {
            const float4* nsrc = (const float4*)neighbor + (size_t)t0 * 2048;
            #pragma unroll
            for (int i = 0; i < 8; ++i)
                cp16(sbase + SM_RAW0 + (uint32_t)(tid + i * NTHREADS) * 16, nsrc + tid + i * NTHREADS);
            if (tid < 128) cp16(sbase + SM_EX + (uint32_t)tid * 16, (const float4*)extra + (size_t)t0 * 128 + tid);
            if (tid < 16)  cp16(sbase + SM_WT + (uint32_t)tid * 16, (const float4*)nweight + (size_t)t0 * 16 + tid);
        }
        cp_commit();
    }

    const uint32_t afbase = sbase + SM_A
        + (uint32_t)((lane & 7) + ((lane >> 3) & 1) * 8) * ASTRIDE
        + (lane >> 4) * 16;

    const int g  = lane >> 2;
    const int i2 = (lane & 3) * 2;
    const int e0 = warp * 16 + i2;
    const float b00 = biass[e0],     b01 = biass[e0 + 1];
    const float b10 = biass[e0 + 8], b11 = biass[e0 + 9];
    const float v00 = w2s[e0],       v01 = w2s[e0 + 1];
    const float v10 = w2s[e0 + 8],   v11 = w2s[e0 + 9];

    const int obn = warp >> 1;               // epilogue: this warp's local bn (0..3)
    const int od0 = (warp & 1) * 64 + lane;  // this thread's two d's: od0, od0+32

    int buf = 0;
    for (int tile = blockIdx.x; tile < ntiles; tile += stride) {
        cp_wait_all();     // only current tile's group is outstanding here
        __syncthreads();   // sync 1: raw[buf] ready AND all prior-buffer reads done

        // ---- now safe: issue next tile's loads into buf^1 (overlaps everything below) ----
        {
            int nxt = tile + stride;
            if (nxt < ntiles) {
                const uint32_t dst = sbase + (buf ? SM_RAW0 : SM_RAW1);
                const float4* nsrc = (const float4*)neighbor + (size_t)nxt * 2048;
                #pragma unroll
                for (int i = 0; i < 8; ++i)
                    cp16(dst + (uint32_t)(tid + i * NTHREADS) * 16, nsrc + tid + i * NTHREADS);
                if (tid < 128) cp16(sbase + SM_EX + (buf ^ 1) * 2048 + (uint32_t)tid * 16,
                                    (const float4*)extra + (size_t)nxt * 128 + tid);
                if (tid < 16)  cp16(sbase + SM_WT + (buf ^ 1) * 256 + (uint32_t)tid * 16,
                                    (const float4*)nweight + (size_t)nxt * 16 + tid);
            }
            cp_commit();
        }

        const uint32_t rawoff = buf ? SM_RAW1 : SM_RAW0;
        const float* exb = (const float*)(smem + SM_EX + buf * 2048);
        const float* wtb = (const float*)(smem + SM_WT + buf * 256);

        // ---- build gated A tile (fp16, ldsm layout) from SMEM raw ----
        #pragma unroll
        for (int i = 0; i < 8; ++i) {
            int idx4 = tid + i * NTHREADS;      // 0..2047
            int m  = idx4 >> 5;                  // M row 0..63
            int q  = idx4 & 31;
            float4 nv = *(const float4*)(smem + rawoff + (uint32_t)idx4 * 16);
            float4 ev = *(const float4*)(exb + ((m >> 4) * 32 + q) * 4);
            uint2 hv;
            hv.x = pack_h2(nv.x * ev.x, nv.y * ev.y);
            hv.y = pack_h2(nv.z * ev.z, nv.w * ev.w);
            *(uint2*)(smem + SM_A + (uint32_t)m * ASTRIDE + (uint32_t)q * 8) = hv;
        }
        __syncthreads();   // sync 2: A ready

        // ---- GEMM: 4 m-tiles x warp's 16-e strip ----
        float c[4][2][4];
        #pragma unroll
        for (int mt = 0; mt < 4; ++mt)
            #pragma unroll
            for (int nt = 0; nt < 2; ++nt)
                { c[mt][nt][0]=0.f; c[mt][nt][1]=0.f; c[mt][nt][2]=0.f; c[mt][nt][3]=0.f; }

        #pragma unroll
        for (int kc = 0; kc < 8; ++kc) {
            #pragma unroll
            for (int mt = 0; mt < 4; ++mt) {
                uint32_t a0, a1, a2, a3;
                ldsm4(a0, a1, a2, a3, afbase + (uint32_t)(mt * 16) * ASTRIDE + kc * 32);
                mma_f16(c[mt][0][0], c[mt][0][1], c[mt][0][2], c[mt][0][3],
                        a0, a1, a2, a3, bb[kc][0], bb[kc][1]);
                mma_f16(c[mt][1][0], c[mt][1][1], c[mt][1][2], c[mt][1][3],
                        a0, a1, a2, a3, bb[kc][2], bb[kc][3]);
            }
        }

        // ---- partial w2-dot into SMEM ----
        #pragma unroll
        for (int mt = 0; mt < 4; ++mt) {
            const float wk0 = wtb[mt * 16 + g];
            const float wk1 = wtb[mt * 16 + g + 8];
            float p0 = leaky02(c[mt][0][0] + wk0 * b00) * v00
                     + leaky02(c[mt][0][1] + wk0 * b01) * v01
                     + leaky02(c[mt][1][0] + wk0 * b10) * v10
                     + leaky02(c[mt][1][1] + wk0 * b11) * v11;
            float p1 = leaky02(c[mt][0][2] + wk1 * b00) * v00
                     + leaky02(c[mt][0][3] + wk1 * b01) * v01
                     + leaky02(c[mt][1][2] + wk1 * b10) * v10
                     + leaky02(c[mt][1][3] + wk1 * b11) * v11;
            p0 += __shfl_xor_sync(0xffffffffu, p0, 1);
            p0 += __shfl_xor_sync(0xffffffffu, p0, 2);
            p1 += __shfl_xor_sync(0xffffffffu, p1, 1);
            p1 += __shfl_xor_sync(0xffffffffu, p1, 2);
            if ((lane & 3) == 0) {
                part[warp * 64 + mt * 16 + g]     = p0;
                part[warp * 64 + mt * 16 + g + 8] = p1;
            }
        }
        __syncthreads();   // sync 3: partials ready

        // ---- ALL warps: redundant reduce + softmax (16-lane groups), output ----
        {
            const int r = obn * 16 + (lane & 15);   // this lane's (bn,k) row
            float s = 0.f;
            #pragma unroll
            for (int pw = 0; pw < 8; ++pw) s += part[pw * 64 + r];

            float mx = s;
            #pragma unroll
            for (int o = 1; o <= 8; o <<= 1)
                mx = fmaxf(mx, __shfl_xor_sync(0xffffffffu, mx, o));
            float ev = __expf(s - mx);
            float es = ev;
            #pragma unroll
            for (int o = 1; o <= 8; o <<= 1)
                es += __shfl_xor_sync(0xffffffffu, es, o);
            float alpha = ev / es;

            float al2[KN];
            #pragma unroll
            for (int k = 0; k < KN; ++k)
                al2[k] = __shfl_sync(0xffffffffu, alpha, k);   // lanes 0-15 hold k

            const float* rbn = (const float*)(smem + rawoff) + obn * (KN * DIMX);
            float acc0 = 0.f, acc1 = 0.f;
            #pragma unroll
            for (int k = 0; k < KN; ++k) {
                acc0 = fmaf(al2[k], rbn[k * DIMX + od0], acc0);
                acc1 = fmaf(al2[k], rbn[k * DIMX + od0 + 32], acc1);
            }
            float* orow = out + ((size_t)tile * TBN + obn) * DIMX;
            orow[od0]      = acc0;
            orow[od0 + 32] = acc1;
        }

        buf ^= 1;
    }
}

extern "C" void kernel_launch(void* const* d_in, const int* in_sizes, int n_in,
                              void* d_out, int out_size) {
    const float* neighbor = (const float*)d_in[1];
    const float* nweight  = (const float*)d_in[4];
    const float* extra    = (const float*)d_in[5];
    const float* w1       = (const float*)d_in[6];
    const float* w2       = (const float*)d_in[7];
    float* out            = (float*)d_out;

    const int total_bn = in_sizes[5] / DIMX;   // 65536
    const int ntiles   = total_bn / TBN;       // 16384

    cudaFuncSetAttribute(agg_mma_kernel, cudaFuncAttributeMaxDynamicSharedMemorySize, SM_TOTAL);
    agg_mma_kernel<<<304, NTHREADS, SM_TOTAL>>>(neighbor, nweight, extra, w1, w2, out, ntiles);
}

// round 17
// speedup vs baseline: 1.1384x; 1.1384x over previous
#include <cuda_runtime.h>
#include <cuda_fp16.h>
#include <cstdint>

// GlobalAggregator: B=256, N=256, K=16, DIM=128
// TBN=4 (M=64), cp.async double-buffered, 2 CTAs/SM, R13 sync skeleton.
// GEMM split 4n x 2m: warp (mg,ng) owns 32 m-rows x 32 e-cols.
//  - B (w1^T fp16) persistent in regs: 64 regs/warp (warp's 32-e strip, all 8 kc)
//  - A-ldsm traffic halved vs 8-way n-split (each warp reads only its 32 rows)

#define DIMX 128
#define KN   16
#define TBN  4
#define NTHREADS 256
#define ASTRIDE 272          // bytes per A/Bt row (128 fp16 + 8 pad)

#define SM_A     0           // 64 x 272 = 17408 (Bt spans A+RAW0 during init)
#define SM_RAW0  17408       // 64x128 f32 = 32768
#define SM_RAW1  50176       // 32768
#define SM_EX    82944       // 2 bufs x 512 f32 = 4096
#define SM_WT    87040       // 2 bufs x 64 f32 = 512
#define SM_PART  87552       // 4 x 64 f32 = 1024
#define SM_BIAS  89600       // 128 f32
#define SM_W2    90112       // 128 f32
#define SM_TOTAL 90624

static __device__ __forceinline__ uint32_t smem_u32(const void* p) {
    uint32_t a;
    asm("{ .reg .u64 t; cvta.to.shared.u64 t, %1; cvt.u32.u64 %0, t; }" : "=r"(a) : "l"(p));
    return a;
}
static __device__ __forceinline__ void cp16(uint32_t saddr, const void* g) {
    asm volatile("cp.async.cg.shared.global [%0], [%1], 16;" :: "r"(saddr), "l"(g));
}
static __device__ __forceinline__ void cp_commit() {
    asm volatile("cp.async.commit_group;" ::: "memory");
}
static __device__ __forceinline__ void cp_wait_all() {
    asm volatile("cp.async.wait_group 0;" ::: "memory");
}
static __device__ __forceinline__ void ldsm4(uint32_t& r0, uint32_t& r1, uint32_t& r2, uint32_t& r3,
                                             uint32_t addr) {
    asm volatile("ldmatrix.sync.aligned.m8n8.x4.shared.b16 {%0,%1,%2,%3}, [%4];"
                 : "=r"(r0), "=r"(r1), "=r"(r2), "=r"(r3) : "r"(addr));
}
static __device__ __forceinline__ void mma_f16(float& c0, float& c1, float& c2, float& c3,
                                               uint32_t a0, uint32_t a1, uint32_t a2, uint32_t a3,
                                               uint32_t b0, uint32_t b1) {
    asm volatile("mma.sync.aligned.m16n8k16.row.col.f32.f16.f16.f32 "
                 "{%0,%1,%2,%3},{%4,%5,%6,%7},{%8,%9},{%0,%1,%2,%3};"
                 : "+f"(c0), "+f"(c1), "+f"(c2), "+f"(c3)
                 : "r"(a0), "r"(a1), "r"(a2), "r"(a3), "r"(b0), "r"(b1));
}
static __device__ __forceinline__ uint32_t pack_h2(float x, float y) {
    __half2 h(__float2half_rn(x), __float2half_rn(y));
    return *(uint32_t*)&h;
}
__device__ __forceinline__ float leaky02(float v) { return v > 0.0f ? v : 0.2f * v; }

extern "C" __global__ void __launch_bounds__(NTHREADS, 2)
agg_mma_kernel(const float* __restrict__ neighbor,
               const float* __restrict__ nweight,
               const float* __restrict__ extra,
               const float* __restrict__ w1,
               const float* __restrict__ w2,
               float* __restrict__ out,
               int ntiles)
{
    extern __shared__ __align__(16) char smem[];
    const uint32_t sbase = smem_u32(smem);
    const int tid  = threadIdx.x;
    const int warp = tid >> 5;
    const int lane = tid & 31;
    const int mg   = warp >> 2;        // m-group: 0/1 (32 rows each)
    const int ng   = warp & 3;         // n-group: 0..3 (32 e-cols each)

    float* part  = (float*)(smem + SM_PART);   // [4 ng][64 rows]
    float* biass = (float*)(smem + SM_BIAS);
    float* w2s   = (float*)(smem + SM_W2);

    // ---- phase 0: build Bt (w1^T fp16) across A+RAW0 region (init only) ----
    for (int idx = tid; idx < DIMX * DIMX; idx += NTHREADS) {
        int d = idx >> 7;
        int e = idx & 127;
        *(__half*)(smem + (uint32_t)e * ASTRIDE + (uint32_t)d * 2) = __float2half_rn(w1[idx]);
    }
    if (tid < DIMX) {
        biass[tid] = w1[DIMX * DIMX + tid];
        w2s[tid]   = w2[tid];
    }
    __syncthreads();

    // ---- persistent B frags: warp's 32-e strip, 8 kc chunks (64 regs) ----
    uint32_t bb[8][8];
    {
        const uint32_t row8 = (lane & 7) + ((lane >> 4) & 1) * 8;
        const uint32_t bf0 = sbase + (uint32_t)(ng * 32 + row8) * ASTRIDE
                           + ((lane >> 3) & 1) * 16;
        #pragma unroll
        for (int kc = 0; kc < 8; ++kc) {
            ldsm4(bb[kc][0], bb[kc][1], bb[kc][2], bb[kc][3], bf0 + kc * 32);
            ldsm4(bb[kc][4], bb[kc][5], bb[kc][6], bb[kc][7], bf0 + 16 * ASTRIDE + kc * 32);
        }
    }
    __syncthreads();   // Bt consumed; region becomes A tile + raw buffers

    const int stride = gridDim.x;

    // ---- prologue: stream first tile into buffer 0 ----
    {
        int t0 = blockIdx.x;
        if (t0 < ntiles) {
            const float4* nsrc = (const float4*)neighbor + (size_t)t0 * 2048;
            #pragma unroll
            for (int i = 0; i < 8; ++i)
                cp16(sbase + SM_RAW0 + (uint32_t)(tid + i * NTHREADS) * 16, nsrc + tid + i * NTHREADS);
            if (tid < 128) cp16(sbase + SM_EX + (uint32_t)tid * 16, (const float4*)extra + (size_t)t0 * 128 + tid);
            if (tid < 16)  cp16(sbase + SM_WT + (uint32_t)tid * 16, (const float4*)nweight + (size_t)t0 * 16 + tid);
        }
        cp_commit();
    }

    // A ldsm base: warp's 32-row half
    const uint32_t afbase = sbase + SM_A
        + (uint32_t)(mg * 32 + (lane & 7) + ((lane >> 3) & 1) * 8) * ASTRIDE
        + (lane >> 4) * 16;

    const int g  = lane >> 2;
    const int i2 = (lane & 3) * 2;

    const int obn = warp >> 1;               // epilogue: this warp's local bn (0..3)
    const int od0 = (warp & 1) * 64 + lane;  // this thread's two d's: od0, od0+32

    int buf = 0;
    for (int tile = blockIdx.x; tile < ntiles; tile += stride) {
        cp_wait_all();
        __syncthreads();   // sync 1: raw[buf] ready

        const uint32_t rawoff = buf ? SM_RAW1 : SM_RAW0;
        const float* exb = (const float*)(smem + SM_EX + buf * 2048);
        const float* wtb = (const float*)(smem + SM_WT + buf * 256);

        // ---- build gated A tile (fp16, ldsm layout) from SMEM raw ----
        #pragma unroll
        for (int i = 0; i < 8; ++i) {
            int idx4 = tid + i * NTHREADS;      // 0..2047
            int m  = idx4 >> 5;                  // M row 0..63
            int q  = idx4 & 31;
            float4 nv = *(const float4*)(smem + rawoff + (uint32_t)idx4 * 16);
            float4 ev = *(const float4*)(exb + ((m >> 4) * 32 + q) * 4);
            uint2 hv;
            hv.x = pack_h2(nv.x * ev.x, nv.y * ev.y);
            hv.y = pack_h2(nv.z * ev.z, nv.w * ev.w);
            *(uint2*)(smem + SM_A + (uint32_t)m * ASTRIDE + (uint32_t)q * 8) = hv;
        }

        // ---- issue next tile's loads (after A-build, R13 placement) ----
        {
            int nxt = tile + stride;
            if (nxt < ntiles) {
                const uint32_t dst = sbase + (buf ? SM_RAW0 : SM_RAW1);
                const float4* nsrc = (const float4*)neighbor + (size_t)nxt * 2048;
                #pragma unroll
                for (int i = 0; i < 8; ++i)
                    cp16(dst + (uint32_t)(tid + i * NTHREADS) * 16, nsrc + tid + i * NTHREADS);
                if (tid < 128) cp16(sbase + SM_EX + (buf ^ 1) * 2048 + (uint32_t)tid * 16,
                                    (const float4*)extra + (size_t)nxt * 128 + tid);
                if (tid < 16)  cp16(sbase + SM_WT + (buf ^ 1) * 256 + (uint32_t)tid * 16,
                                    (const float4*)nweight + (size_t)nxt * 16 + tid);
            }
            cp_commit();
        }
        __syncthreads();   // sync 2: A ready

        // ---- GEMM: 2 m-tiles x 4 n-tiles (warp's 32 rows x 32 e) ----
        float c[2][4][4];
        #pragma unroll
        for (int mt = 0; mt < 2; ++mt)
            #pragma unroll
            for (int nt = 0; nt < 4; ++nt)
                { c[mt][nt][0]=0.f; c[mt][nt][1]=0.f; c[mt][nt][2]=0.f; c[mt][nt][3]=0.f; }

        #pragma unroll
        for (int kc = 0; kc < 8; ++kc) {
            #pragma unroll
            for (int mt = 0; mt < 2; ++mt) {
                uint32_t a0, a1, a2, a3;
                ldsm4(a0, a1, a2, a3, afbase + (uint32_t)(mt * 16) * ASTRIDE + kc * 32);
                mma_f16(c[mt][0][0], c[mt][0][1], c[mt][0][2], c[mt][0][3],
                        a0, a1, a2, a3, bb[kc][0], bb[kc][1]);
                mma_f16(c[mt][1][0], c[mt][1][1], c[mt][1][2], c[mt][1][3],
                        a0, a1, a2, a3, bb[kc][2], bb[kc][3]);
                mma_f16(c[mt][2][0], c[mt][2][1], c[mt][2][2], c[mt][2][3],
                        a0, a1, a2, a3, bb[kc][4], bb[kc][5]);
                mma_f16(c[mt][3][0], c[mt][3][1], c[mt][3][2], c[mt][3][3],
                        a0, a1, a2, a3, bb[kc][6], bb[kc][7]);
            }
        }

        // ---- partial w2-dot (warp's 32 e) into part[ng][row] ----
        #pragma unroll
        for (int mt = 0; mt < 2; ++mt) {
            const int r0 = mg * 32 + mt * 16 + g;      // global row of p0 (p1 = +8)
            const float wk0 = wtb[r0];
            const float wk1 = wtb[r0 + 8];
            float p0 = 0.f, p1 = 0.f;
            #pragma unroll
            for (int nt = 0; nt < 4; ++nt) {
                const int e = ng * 32 + nt * 8 + i2;
                const float be0 = biass[e], be1 = biass[e + 1];
                const float ve0 = w2s[e],  ve1 = w2s[e + 1];
                p0 = fmaf(leaky02(c[mt][nt][0] + wk0 * be0), ve0, p0);
                p0 = fmaf(leaky02(c[mt][nt][1] + wk0 * be1), ve1, p0);
                p1 = fmaf(leaky02(c[mt][nt][2] + wk1 * be0), ve0, p1);
                p1 = fmaf(leaky02(c[mt][nt][3] + wk1 * be1), ve1, p1);
            }
            p0 += __shfl_xor_sync(0xffffffffu, p0, 1);
            p0 += __shfl_xor_sync(0xffffffffu, p0, 2);
            p1 += __shfl_xor_sync(0xffffffffu, p1, 1);
            p1 += __shfl_xor_sync(0xffffffffu, p1, 2);
            if ((lane & 3) == 0) {
                part[ng * 64 + r0]     = p0;
                part[ng * 64 + r0 + 8] = p1;
            }
        }
        __syncthreads();   // sync 3: partials ready

        // ---- ALL warps: reduce over 4 n-groups, softmax (16-lane groups), output ----
        {
            const int r = obn * 16 + (lane & 15);
            float s = part[0 * 64 + r] + part[1 * 64 + r]
                    + part[2 * 64 + r] + part[3 * 64 + r];

            float mx = s;
            #pragma unroll
            for (int o = 1; o <= 8; o <<= 1)
                mx = fmaxf(mx, __shfl_xor_sync(0xffffffffu, mx, o));
            float ev = __expf(s - mx);
            float es = ev;
            #pragma unroll
            for (int o = 1; o <= 8; o <<= 1)
                es += __shfl_xor_sync(0xffffffffu, es, o);
            float alpha = ev / es;

            float al2[KN];
            #pragma unroll
            for (int k = 0; k < KN; ++k)
                al2[k] = __shfl_sync(0xffffffffu, alpha, k);

            const float* rbn = (const float*)(smem + rawoff) + obn * (KN * DIMX);
            float acc0 = 0.f, acc1 = 0.f;
            #pragma unroll
            for (int k = 0; k < KN; ++k) {
                acc0 = fmaf(al2[k], rbn[k * DIMX + od0], acc0);
                acc1 = fmaf(al2[k], rbn[k * DIMX + od0 + 32], acc1);
            }
            float* orow = out + ((size_t)tile * TBN + obn) * DIMX;
            orow[od0]      = acc0;
            orow[od0 + 32] = acc1;
        }

        buf ^= 1;
        __syncthreads();   // sync 4: all reads of raw[buf_old]/part done
    }
}

extern "C" void kernel_launch(void* const* d_in, const int* in_sizes, int n_in,
                              void* d_out, int out_size) {
    const float* neighbor = (const float*)d_in[1];
    const float* nweight  = (const float*)d_in[4];
    const float* extra    = (const float*)d_in[5];
    const float* w1       = (const float*)d_in[6];
    const float* w2       = (const float*)d_in[7];
    float* out            = (float*)d_out;

    const int total_bn = in_sizes[5] / DIMX;   // 65536
    const int ntiles   = total_bn / TBN;       // 16384

    cudaFuncSetAttribute(agg_mma_kernel, cudaFuncAttributeMaxDynamicSharedMemorySize, SM_TOTAL);
    agg_mma_kernel<<<304, NTHREADS, SM_TOTAL>>>(neighbor, nweight, extra, w1, w2, out, ntiles);
}